// round 1
// baseline (speedup 1.0000x reference)
#include <cuda_runtime.h>
#include <math.h>

#define BB 32
#define TT 4096
#define FF 256
#define KSEL 409            // max(1, int(4096*0.1))
#define NCHUNK 32
#define TCHUNK (TT/NCHUNK)  // 128
#define EMPH 1.5f

__device__ float g_e[BB*TT];
__device__ float g_s[BB*TT];
__device__ float g_part[BB*NCHUNK*FF];

// ---------------- K1: e[b,t] = tanh(dot(x[b,t,:], W) + bias) ----------------
// warp per row; each lane loads 2 float4 (covers 256 floats), warp-reduce.
__global__ void __launch_bounds__(256) k1_dot(const float* __restrict__ x,
                                              const float* __restrict__ W,
                                              const float* __restrict__ bias) {
    int gwarp = (blockIdx.x * blockDim.x + threadIdx.x) >> 5;
    int lane  = threadIdx.x & 31;
    if (gwarp >= BB*TT) return;
    const float4* xr = (const float4*)(x + (size_t)gwarp * FF);
    const float4* wr = (const float4*)W;
    float4 a0 = xr[lane];
    float4 a1 = xr[lane + 32];
    float4 w0 = __ldg(&wr[lane]);
    float4 w1 = __ldg(&wr[lane + 32]);
    float s = a0.x*w0.x + a0.y*w0.y + a0.z*w0.z + a0.w*w0.w
            + a1.x*w1.x + a1.y*w1.y + a1.z*w1.z + a1.w*w1.w;
    #pragma unroll
    for (int o = 16; o; o >>= 1) s += __shfl_xor_sync(0xffffffffu, s, o);
    if (lane == 0) g_e[gwarp] = tanhf(s + bias[0]);
}

// ---------------- K2: per-batch softmax denom + exact k-th largest ----------
// one block per batch, 512 threads, 8 keys/thread in registers.
__device__ __forceinline__ unsigned f2key(float f) {
    unsigned u = __float_as_uint(f);
    return u ^ ((u >> 31) ? 0xFFFFFFFFu : 0x80000000u);  // monotone transform
}

__global__ void __launch_bounds__(512) k2_select(void) {
    __shared__ float red[512];
    __shared__ unsigned cnt_sh;
    const int b = blockIdx.x, tid = threadIdx.x;

    float ev[8];
    unsigned key[8];
    float zsum = 0.f;
    #pragma unroll
    for (int i = 0; i < 8; i++) {
        float e = g_e[b*TT + tid + i*512];
        ev[i] = e;
        key[i] = f2key(e);
        zsum += __expf(e - 1.0f);          // fixed max: tanh <= 1
    }
    red[tid] = zsum;
    __syncthreads();
    #pragma unroll
    for (int o = 256; o; o >>= 1) {
        if (tid < o) red[tid] += red[tid + o];
        __syncthreads();
    }
    const float invZ = 1.0f / red[0];

    // radix bisection: largest v with count(key >= v) >= KSEL  == k-th largest
    unsigned prefix = 0;
    for (int bit = 31; bit >= 0; bit--) {
        unsigned test = prefix | (1u << bit);
        if (tid == 0) cnt_sh = 0;
        __syncthreads();
        unsigned c = 0;
        #pragma unroll
        for (int i = 0; i < 8; i++) c += (key[i] >= test);
        #pragma unroll
        for (int o = 16; o; o >>= 1) c += __shfl_xor_sync(0xffffffffu, c, o);
        if ((tid & 31) == 0) atomicAdd(&cnt_sh, c);
        __syncthreads();
        unsigned total = cnt_sh;
        __syncthreads();                    // protect cnt_sh before next reset
        if (total >= KSEL) prefix = test;
    }

    #pragma unroll
    for (int i = 0; i < 8; i++) {
        float a = __expf(ev[i] - 1.0f) * invZ;
        g_s[b*TT + tid + i*512] = (key[i] >= prefix) ? a * EMPH : a;
    }
}

// ---------------- K3: partial weighted sums over t-chunks -------------------
__global__ void __launch_bounds__(256) k3_wsum(const float* __restrict__ x) {
    const int c = blockIdx.x;      // t-chunk
    const int b = blockIdx.y;      // batch
    const int f = threadIdx.x;     // feature
    __shared__ float ssc[TCHUNK];
    const int t0 = c * TCHUNK;
    if (f < TCHUNK) ssc[f] = g_s[b*TT + t0 + f];
    __syncthreads();
    const float* xp = x + ((size_t)b*TT + t0) * FF + f;
    float acc = 0.f;
    #pragma unroll 8
    for (int i = 0; i < TCHUNK; i++) acc += xp[(size_t)i*FF] * ssc[i];
    g_part[(b*NCHUNK + c)*FF + f] = acc;
}

// ---------------- K4: reduce partials -> out [B,1,F] ------------------------
__global__ void __launch_bounds__(256) k4_reduce(float* __restrict__ out) {
    const int b = blockIdx.x, f = threadIdx.x;
    float s = 0.f;
    #pragma unroll
    for (int c = 0; c < NCHUNK; c++) s += g_part[(b*NCHUNK + c)*FF + f];
    out[b*FF + f] = s;
}

extern "C" void kernel_launch(void* const* d_in, const int* in_sizes, int n_in,
                              void* d_out, int out_size) {
    const float* x    = (const float*)d_in[0];
    const float* W    = (const float*)d_in[1];
    const float* bias = (const float*)d_in[2];
    float* out = (float*)d_out;

    // K1: BB*TT rows, 8 warps (rows) per 256-thread block
    k1_dot<<<(BB*TT)/8, 256>>>(x, W, bias);
    k2_select<<<BB, 512>>>();
    dim3 g3(NCHUNK, BB);
    k3_wsum<<<g3, 256>>>(x);
    k4_reduce<<<BB, 256>>>(out);
}